// round 1
// baseline (speedup 1.0000x reference)
#include <cuda_runtime.h>
#include <math.h>
#include <stdint.h>

#define BS 32
#define NQ 900
#define NC 91
#define NT 30
#define NTT (BS * NT)   // 960 total targets
#define QPB 32          // q-rows per block in cost kernel
#define LSA_THREADS 256

// ---------------------------------------------------------------------------
// Kernel 1: cost matrix C3[b, q, j] for all 960 targets j.
// One block handles QPB q's for one batch b; 8 warps, each warp owns q's.
// ---------------------------------------------------------------------------
__global__ void __launch_bounds__(256) cost_kernel(
    const float* __restrict__ logits,   // (BS, NQ, NC)
    const float* __restrict__ pboxes,   // (BS, NQ, 4) cxcywh
    const int*   __restrict__ tlabels,  // (BS, NT)
    const float* __restrict__ tboxes,   // (BS, NT, 4) cxcywh
    float* __restrict__ out)            // (BS, NQ, NTT)
{
    __shared__ float s_traw[NTT * 4];   // raw cxcywh
    __shared__ float s_txy[NTT * 4];    // xyxy
    __shared__ float s_tarea[NTT];
    __shared__ int   s_tlab[NTT];
    __shared__ float s_prob[8][92];     // per-warp softmax probs

    const int b     = blockIdx.y;
    const int qbase = blockIdx.x * QPB;
    const int tid   = threadIdx.x;

    // Stage all 960 targets into shared
    for (int j = tid; j < NTT; j += blockDim.x) {
        float cx = tboxes[j * 4 + 0];
        float cy = tboxes[j * 4 + 1];
        float w  = tboxes[j * 4 + 2];
        float h  = tboxes[j * 4 + 3];
        s_traw[j * 4 + 0] = cx; s_traw[j * 4 + 1] = cy;
        s_traw[j * 4 + 2] = w;  s_traw[j * 4 + 3] = h;
        float x0 = cx - 0.5f * w, y0 = cy - 0.5f * h;
        float x1 = cx + 0.5f * w, y1 = cy + 0.5f * h;
        s_txy[j * 4 + 0] = x0; s_txy[j * 4 + 1] = y0;
        s_txy[j * 4 + 2] = x1; s_txy[j * 4 + 3] = y1;
        s_tarea[j] = (x1 - x0) * (y1 - y0);
        s_tlab[j] = tlabels[j];
    }
    __syncthreads();

    const int warp = tid >> 5;
    const int lane = tid & 31;

    for (int qi = warp; qi < QPB; qi += 8) {
        const int q = qbase + qi;
        if (q >= NQ) continue;

        // --- softmax over 91 classes (warp-collective) ---
        const float* lg = logits + ((size_t)b * NQ + q) * NC;
        float x0 = (lane      < NC) ? lg[lane]      : -1e30f;
        float x1 = (lane + 32 < NC) ? lg[lane + 32] : -1e30f;
        float x2 = (lane + 64 < NC) ? lg[lane + 64] : -1e30f;
        float m = fmaxf(x0, fmaxf(x1, x2));
        #pragma unroll
        for (int o = 16; o > 0; o >>= 1) m = fmaxf(m, __shfl_xor_sync(0xffffffffu, m, o));
        float e0 = (lane      < NC) ? expf(x0 - m) : 0.f;
        float e1 = (lane + 32 < NC) ? expf(x1 - m) : 0.f;
        float e2 = (lane + 64 < NC) ? expf(x2 - m) : 0.f;
        float s = e0 + e1 + e2;
        #pragma unroll
        for (int o = 16; o > 0; o >>= 1) s += __shfl_xor_sync(0xffffffffu, s, o);
        float inv = 1.0f / s;
        if (lane      < NC) s_prob[warp][lane]      = e0 * inv;
        if (lane + 32 < NC) s_prob[warp][lane + 32] = e1 * inv;
        if (lane + 64 < NC) s_prob[warp][lane + 64] = e2 * inv;
        __syncwarp();

        // --- pred box ---
        const float* pb = pboxes + ((size_t)b * NQ + q) * 4;
        float pcx = pb[0], pcy = pb[1], pw = pb[2], ph = pb[3];
        float px0 = pcx - 0.5f * pw, py0 = pcy - 0.5f * ph;
        float px1 = pcx + 0.5f * pw, py1 = pcy + 0.5f * ph;
        float parea = (px1 - px0) * (py1 - py0);

        float* orow = out + ((size_t)b * NQ + q) * NTT;
        for (int j = lane; j < NTT; j += 32) {
            float cc = 1.0f - s_prob[warp][s_tlab[j]];
            float cb = fabsf(pcx - s_traw[j * 4 + 0]) + fabsf(pcy - s_traw[j * 4 + 1])
                     + fabsf(pw  - s_traw[j * 4 + 2]) + fabsf(ph  - s_traw[j * 4 + 3]);
            float tx0 = s_txy[j * 4 + 0], ty0 = s_txy[j * 4 + 1];
            float tx1 = s_txy[j * 4 + 2], ty1 = s_txy[j * 4 + 3];
            float iw = fmaxf(fminf(px1, tx1) - fmaxf(px0, tx0), 0.f);
            float ih = fmaxf(fminf(py1, ty1) - fmaxf(py0, ty0), 0.f);
            float inter = iw * ih;
            float uni = parea + s_tarea[j] - inter;
            float iou = inter / uni;
            float ew = fmaxf(fmaxf(px1, tx1) - fminf(px0, tx0), 0.f);
            float eh = fmaxf(fmaxf(py1, ty1) - fminf(py0, ty0), 0.f);
            float encl = ew * eh;
            float giou = iou - (encl - uni) / encl;
            orow[j] = 5.0f * cb + cc + 2.0f * (1.0f - giou);
        }
    }
}

// ---------------------------------------------------------------------------
// Kernel 2: per-batch Hungarian (JV shortest augmenting path), one block each.
// Cost slice (30 x 900) staged into shared as float (identical bits to C3),
// dual potentials in double to match the reference float64 arithmetic.
// ---------------------------------------------------------------------------
extern __shared__ unsigned char lsa_sh[];

__global__ void __launch_bounds__(LSA_THREADS) lsa_kernel(
    const float* __restrict__ C3,
    float* __restrict__ out_pred,
    float* __restrict__ out_tgt)
{
    const int bi  = blockIdx.x;
    const int tid = threadIdx.x;

    // carve shared
    float*  cst  = (float*)lsa_sh;                       // NT*NQ floats
    double* v    = (double*)(cst + NT * NQ);             // NQ+1
    double* minv = v + (NQ + 1);                         // NQ+1
    double* u    = minv + (NQ + 1);                      // NT+1
    double* rval = u + (NT + 1);                         // LSA_THREADS
    int* way  = (int*)(rval + LSA_THREADS);              // NQ+1
    int* p    = way + (NQ + 1);                          // NQ+1
    int* used = p + (NQ + 1);                            // NQ+1
    int* ridx = used + (NQ + 1);                         // LSA_THREADS

    __shared__ int s_j0;
    __shared__ int s_done;
    __shared__ double s_delta;
    __shared__ int s_j1;
    __shared__ int rows[NT];
    __shared__ int ord[NT];

    // load cost slice, transposed to [t][q]; source C3[bi, q, bi*NT + t]
    const float* base = C3 + (size_t)bi * NQ * NTT + (size_t)bi * NT;
    for (int idx = tid; idx < NT * NQ; idx += LSA_THREADS) {
        int j = idx / NT;
        int t = idx % NT;
        cst[t * NQ + j] = base[(size_t)j * NTT + t];
    }
    for (int j = tid; j <= NQ; j += LSA_THREADS) { v[j] = 0.0; p[j] = 0; way[j] = 0; }
    for (int t = tid; t <= NT; t += LSA_THREADS) u[t] = 0.0;
    __syncthreads();

    for (int i = 1; i <= NT; i++) {
        for (int j = tid; j <= NQ; j += LSA_THREADS) { minv[j] = 1e18; used[j] = 0; }
        if (tid == 0) { p[0] = i; s_j0 = 0; }
        __syncthreads();

        while (true) {
            const int j0 = s_j0;
            if (tid == 0) used[j0] = 1;
            __syncthreads();
            const int i0 = p[j0];
            const double ui0 = u[i0];
            const float* crow = cst + (i0 - 1) * NQ;

            // scan: update minv/way; compute local min over unused
            double lmin = 1e18;
            int lidx = 0;
            #pragma unroll
            for (int k = 0; k < 4; k++) {
                int j = tid + 1 + k * LSA_THREADS;
                if (j <= NQ && !used[j]) {
                    double cur = (double)crow[j - 1] - ui0 - v[j];
                    if (cur < minv[j]) { minv[j] = cur; way[j] = j0; }
                    double mv = minv[j];
                    if (mv < lmin) { lmin = mv; lidx = j; }
                }
            }
            rval[tid] = lmin; ridx[tid] = lidx;
            __syncthreads();
            // tree reduce, lowest-index tiebreak (matches np.argmin)
            for (int s = LSA_THREADS / 2; s > 0; s >>= 1) {
                if (tid < s) {
                    double ov = rval[tid + s]; int oi = ridx[tid + s];
                    double mv = rval[tid];     int mi = ridx[tid];
                    if (ov < mv || (ov == mv && oi < mi)) { rval[tid] = ov; ridx[tid] = oi; }
                }
                __syncthreads();
            }
            if (tid == 0) { s_j1 = ridx[0]; s_delta = rval[0]; }
            __syncthreads();
            const double delta = s_delta;
            const int j1 = s_j1;

            // dual updates (distinct u targets per used column -> race-free)
            #pragma unroll
            for (int k = 0; k < 4; k++) {
                int j = tid + k * LSA_THREADS;
                if (j <= NQ) {
                    if (used[j]) { u[p[j]] += delta; v[j] -= delta; }
                    else if (j >= 1) minv[j] -= delta;
                }
            }
            __syncthreads();
            if (tid == 0) { s_j0 = j1; s_done = (p[j1] == 0); }
            __syncthreads();
            if (s_done) break;
        }
        // augment
        if (tid == 0) {
            int j0 = s_j0;
            while (j0) { int jj = way[j0]; p[j0] = p[jj]; j0 = jj; }
        }
        __syncthreads();
    }

    if (tid == 0) {
        for (int j = 1; j <= NQ; j++)
            if (p[j] > 0) rows[p[j] - 1] = j - 1;
        // stable insertion argsort of rows (values distinct anyway)
        for (int k = 0; k < NT; k++) ord[k] = k;
        for (int a = 1; a < NT; a++) {
            int key = ord[a]; int kv = rows[key]; int b2 = a - 1;
            while (b2 >= 0 && rows[ord[b2]] > kv) { ord[b2 + 1] = ord[b2]; b2--; }
            ord[b2 + 1] = key;
        }
        for (int k = 0; k < NT; k++) {
            out_pred[bi * NT + k] = (float)rows[ord[k]];
            out_tgt[bi * NT + k]  = (float)ord[k];
        }
    }
}

// ---------------------------------------------------------------------------
extern "C" void kernel_launch(void* const* d_in, const int* in_sizes, int n_in,
                              void* d_out, int out_size)
{
    const float* logits  = (const float*)d_in[0];
    const float* pboxes  = (const float*)d_in[1];
    const int*   tlabels = (const int*)d_in[2];
    const float* tboxes  = (const float*)d_in[3];
    float* out = (float*)d_out;

    dim3 grid((NQ + QPB - 1) / QPB, BS);
    cost_kernel<<<grid, 256>>>(logits, pboxes, tlabels, tboxes, out);

    const size_t lsa_smem =
        (size_t)NT * NQ * sizeof(float)
        + (2 * (NQ + 1) + (NT + 1) + LSA_THREADS) * sizeof(double)
        + (3 * (NQ + 1) + LSA_THREADS) * sizeof(int);
    cudaFuncSetAttribute(lsa_kernel, cudaFuncAttributeMaxDynamicSharedMemorySize,
                         (int)lsa_smem);

    float* out_pred = out + (size_t)BS * NQ * NTT;
    float* out_tgt  = out_pred + (size_t)BS * NT;
    lsa_kernel<<<BS, LSA_THREADS, lsa_smem>>>(out, out_pred, out_tgt);
}